// round 5
// baseline (speedup 1.0000x reference)
#include <cuda_runtime.h>

// Problem constants
#define B_ 8
#define S_ 1024
#define D_ 256
#define NR (B_*S_)   // 8192 rows

// Scratch (static device allocations — allowed)
__device__ float g_xq[NR*D_];          // rope(q)  [b,s,d]   8 MB
__device__ float g_xv[NR*D_];          // rope(v)  [b,s,d]   8 MB
__device__ float g_M [B_*16*16*16];    // M[b,h][e][f] (scaled by 1/sqrt(hd))
__device__ float g_W2[B_*D_*D_];       // per-batch effective weight, TRANSPOSED [n][k]

// ---------------------------------------------------------------------------
// tf32 MMA helpers (m16n8k8, row.col, f32 accum) + 3xTF32 split for accuracy
// ---------------------------------------------------------------------------
__device__ __forceinline__ unsigned f2tf(float x){
    unsigned r; asm("cvt.rna.tf32.f32 %0, %1;" : "=r"(r) : "f"(x)); return r;
}
__device__ __forceinline__ uint2 splt(float x){
    unsigned h = f2tf(x);
    unsigned l = f2tf(x - __uint_as_float(h));
    return make_uint2(h, l);
}
__device__ __forceinline__ void mma_tf32(float* d, const unsigned* a, const unsigned* b){
    asm volatile(
        "mma.sync.aligned.m16n8k8.row.col.f32.tf32.tf32.f32 "
        "{%0,%1,%2,%3}, {%4,%5,%6,%7}, {%8,%9}, {%0,%1,%2,%3};"
        : "+f"(d[0]), "+f"(d[1]), "+f"(d[2]), "+f"(d[3])
        : "r"(a[0]), "r"(a[1]), "r"(a[2]), "r"(a[3]),
          "r"(b[0]), "r"(b[1]));
}

// Shared GEMM core: BM=128 BN=64 BK=16, 8 warps (4m x 2n), warp tile 32x32.
// Tiles stored pre-split as uint2{hi,lo}, pitch 20, k-index swizzle k^(row&3):
// conflict-free for both the store phase and the fragment-read phase.

// ---------------------------------------------------------------------------
// K1: fused Q/V projection (C = X @ W^T) + bias + RoPE -> g_xq / g_xv
// grid (64, 8): y<4 -> Q cols [y*64..), y>=4 -> V.
// ---------------------------------------------------------------------------
__global__ __launch_bounds__(256) void qv_rope_tc(
    const float* __restrict__ X,
    const float* __restrict__ Wq, const float* __restrict__ bq,
    const float* __restrict__ Wv, const float* __restrict__ bv)
{
    __shared__ __align__(16) uint2 As[128][20];   // [m][k] split tiles
    __shared__ __align__(16) uint2 Bs[64][20];    // [n][k]
    const int t = threadIdx.x;
    const int lane = t & 31, warp = t >> 5;
    const int g = lane >> 2, tg = lane & 3;
    const int sx = g & 3;                          // read-side swizzle
    const int wm = warp & 3, wn = warp >> 2;
    const int m0 = blockIdx.x * 128;
    const bool isQ = blockIdx.y < 4;
    const int nb = (blockIdx.y & 3) * 64;
    const float* __restrict__ W    = isQ ? Wq : Wv;
    const float* __restrict__ bias = isQ ? bq : bv;
    float* __restrict__ dst        = isQ ? g_xq : g_xv;

    // Store-phase indices
    const int arow0 = t >> 2;           // A float4 #1: rows 0..63
    const int arow1 = (t + 256) >> 2;   // A float4 #2: rows 64..127
    const int ac4   = (t & 3) * 4;
    const int brow  = t >> 2;           // B: rows 0..63
    const int bc4   = (t & 3) * 4;

    float acc[2][4][4] = {};
    float4 aR0, aR1, bR;

    // prefetch kt=0
    aR0 = *(const float4*)(X + (m0+arow0)*D_ + ac4);
    aR1 = *(const float4*)(X + (m0+arow1)*D_ + ac4);
    bR  = *(const float4*)(W + (nb+brow)*D_ + bc4);

    for (int kt = 0; kt < D_; kt += 16) {
        // convert + store (swizzled)
        {
            int p0 = arow0 & 3, p1 = arow1 & 3, pb = brow & 3;
            As[arow0][ac4 + (0^p0)] = splt(aR0.x);
            As[arow0][ac4 + (1^p0)] = splt(aR0.y);
            As[arow0][ac4 + (2^p0)] = splt(aR0.z);
            As[arow0][ac4 + (3^p0)] = splt(aR0.w);
            As[arow1][ac4 + (0^p1)] = splt(aR1.x);
            As[arow1][ac4 + (1^p1)] = splt(aR1.y);
            As[arow1][ac4 + (2^p1)] = splt(aR1.z);
            As[arow1][ac4 + (3^p1)] = splt(aR1.w);
            Bs[brow][bc4 + (0^pb)] = splt(bR.x);
            Bs[brow][bc4 + (1^pb)] = splt(bR.y);
            Bs[brow][bc4 + (2^pb)] = splt(bR.z);
            Bs[brow][bc4 + (3^pb)] = splt(bR.w);
        }
        __syncthreads();
        if (kt + 16 < D_) {
            aR0 = *(const float4*)(X + (m0+arow0)*D_ + kt+16 + ac4);
            aR1 = *(const float4*)(X + (m0+arow1)*D_ + kt+16 + ac4);
            bR  = *(const float4*)(W + (nb+brow)*D_ + kt+16 + bc4);
        }
        #pragma unroll
        for (int ks = 0; ks < 2; ks++) {
            const int k0 = ks*8 + (tg ^ sx), k1 = k0 + 4;
            unsigned aH[2][4], aL[2][4], bH[4][2], bL[4][2];
            #pragma unroll
            for (int mi = 0; mi < 2; mi++) {
                int r0 = wm*32 + mi*16 + g;
                uint2 p;
                p = As[r0  ][k0]; aH[mi][0]=p.x; aL[mi][0]=p.y;
                p = As[r0+8][k0]; aH[mi][1]=p.x; aL[mi][1]=p.y;
                p = As[r0  ][k1]; aH[mi][2]=p.x; aL[mi][2]=p.y;
                p = As[r0+8][k1]; aH[mi][3]=p.x; aL[mi][3]=p.y;
            }
            #pragma unroll
            for (int ni = 0; ni < 4; ni++) {
                int nn = wn*32 + ni*8 + g;
                uint2 p;
                p = Bs[nn][k0]; bH[ni][0]=p.x; bL[ni][0]=p.y;
                p = Bs[nn][k1]; bH[ni][1]=p.x; bL[ni][1]=p.y;
            }
            #pragma unroll
            for (int mi = 0; mi < 2; mi++)
                #pragma unroll
                for (int ni = 0; ni < 4; ni++) {
                    mma_tf32(acc[mi][ni], aH[mi], bH[ni]);
                    mma_tf32(acc[mi][ni], aH[mi], bL[ni]);
                    mma_tf32(acc[mi][ni], aL[mi], bH[ni]);
                }
        }
        __syncthreads();
    }

    // Epilogue: bias + RoPE. theta is uniform per block (nb-aligned halves).
    const float th = (nb < 128) ? 1.0f : 1e-4f;
    #pragma unroll
    for (int mi = 0; mi < 2; mi++) {
        #pragma unroll
        for (int half = 0; half < 2; half++) {
            int r = m0 + wm*32 + mi*16 + g + half*8;
            float pos = (float)((r & (S_-1)) + 1);     // 1-indexed position
            float sv, cv; sincosf(pos * th, &sv, &cv);
            #pragma unroll
            for (int ni = 0; ni < 4; ni++) {
                int d = nb + wn*32 + ni*8 + 2*tg;
                float xe = acc[mi][ni][half*2+0] + bias[d];
                float xo = acc[mi][ni][half*2+1] + bias[d+1];
                float2 o = make_float2(xe*sv - xo*cv, xe*cv + xo*sv);
                *(float2*)(dst + r*D_ + d) = o;
            }
        }
    }
}

// ---------------------------------------------------------------------------
// K2: M[b,h][e][f] = (1/sqrt(16)) * sum_s xq[b,s,16h+e]*xv[b,s,16h+f]
// ---------------------------------------------------------------------------
__global__ __launch_bounds__(256) void m_kernel()
{
    const int bh = blockIdx.x, b = bh >> 4, h = bh & 15;
    const float* __restrict__ q = g_xq + b*S_*D_ + h*16;
    const float* __restrict__ v = g_xv + b*S_*D_ + h*16;
    __shared__ __align__(16) float qs[128][20];
    __shared__ __align__(16) float vs[128][20];
    __shared__ float part[16][16][17];
    const int t = threadIdx.x;
    const int g = t >> 4, lt = t & 15;
    const int e4 = (lt >> 2) * 4, f4 = (lt & 3) * 4;
    float c[4][4] = {};

    for (int chunk = 0; chunk < 8; chunk++) {
        int sb = chunk * 128;
        #pragma unroll
        for (int i = 0; i < 2; i++) {
            int idx = t + i*256;
            int row = idx >> 2, c4 = (idx & 3) * 4;
            *(float4*)&qs[row][c4] = *(const float4*)(q + (sb+row)*D_ + c4);
            *(float4*)&vs[row][c4] = *(const float4*)(v + (sb+row)*D_ + c4);
        }
        __syncthreads();
        int r0 = g * 8;
        #pragma unroll
        for (int ss = 0; ss < 8; ss++) {
            float4 q4 = *(const float4*)&qs[r0+ss][e4];
            float4 v4 = *(const float4*)&vs[r0+ss][f4];
            c[0][0] += q4.x*v4.x; c[0][1] += q4.x*v4.y; c[0][2] += q4.x*v4.z; c[0][3] += q4.x*v4.w;
            c[1][0] += q4.y*v4.x; c[1][1] += q4.y*v4.y; c[1][2] += q4.y*v4.z; c[1][3] += q4.y*v4.w;
            c[2][0] += q4.z*v4.x; c[2][1] += q4.z*v4.y; c[2][2] += q4.z*v4.z; c[2][3] += q4.z*v4.w;
            c[3][0] += q4.w*v4.x; c[3][1] += q4.w*v4.y; c[3][2] += q4.w*v4.z; c[3][3] += q4.w*v4.w;
        }
        __syncthreads();
    }
    #pragma unroll
    for (int i = 0; i < 4; i++)
        #pragma unroll
        for (int j = 0; j < 4; j++)
            part[g][e4+i][f4+j] = c[i][j];
    __syncthreads();
    int e = t >> 4, f = t & 15;
    float s = 0.f;
    #pragma unroll
    for (int gg = 0; gg < 16; gg++) s += part[gg][e][f];
    g_M[bh*256 + t] = s * 0.25f;   // 1/sqrt(HD=16)
}

// ---------------------------------------------------------------------------
// K3: W2T[b][n][16h+e] = sum_f M[b,h][e][f] * wo[n][16h+f]   (transposed out)
// ---------------------------------------------------------------------------
__global__ __launch_bounds__(256) void w2_kernel(const float* __restrict__ Wo)
{
    const int bh = blockIdx.x, b = bh >> 4, h = bh & 15;
    __shared__ __align__(16) float wos[256][20];
    __shared__ float Ms[16][16];
    const int t = threadIdx.x;
    Ms[t >> 4][t & 15] = g_M[bh*256 + t];
    #pragma unroll
    for (int i = 0; i < 4; i++) {
        int idx = t + i*256;
        int row = idx >> 2, c4 = (idx & 3) * 4;
        *(float4*)&wos[row][c4] = *(const float4*)(Wo + row*D_ + h*16 + c4);
    }
    __syncthreads();
    const int n = t;
    float vals[16];
    #pragma unroll
    for (int e = 0; e < 16; e++) {
        float a = 0.f;
        #pragma unroll
        for (int f = 0; f < 16; f++) a += Ms[e][f] * wos[n][f];
        vals[e] = a;
    }
    float* outp = g_W2 + b*D_*D_ + n*D_ + h*16;   // [n][k] layout
    #pragma unroll
    for (int e4 = 0; e4 < 16; e4 += 4)
        *(float4*)(outp + e4) = make_float4(vals[e4], vals[e4+1], vals[e4+2], vals[e4+3]);
}

// ---------------------------------------------------------------------------
// K4: out_b = xq_b @ W2T_b^T + bo  — identical NT structure to K1 now.
// grid (4, 8, 8): x = n-block, y = m-block(128), z = batch.
// ---------------------------------------------------------------------------
__global__ __launch_bounds__(256) void out_tc(
    const float* __restrict__ bo, float* __restrict__ out)
{
    __shared__ __align__(16) uint2 As[128][20];
    __shared__ __align__(16) uint2 Bs[64][20];
    const int t = threadIdx.x;
    const int lane = t & 31, warp = t >> 5;
    const int g = lane >> 2, tg = lane & 3;
    const int sx = g & 3;
    const int wm = warp & 3, wn = warp >> 2;
    const int bz = blockIdx.z;
    const int m0 = blockIdx.y * 128, n0 = blockIdx.x * 64;
    const float* __restrict__ A  = g_xq + bz*S_*D_;
    const float* __restrict__ Bw = g_W2 + bz*D_*D_;   // [n][k]

    const int arow0 = t >> 2;
    const int arow1 = (t + 256) >> 2;
    const int ac4   = (t & 3) * 4;
    const int brow  = t >> 2;
    const int bc4   = (t & 3) * 4;

    float acc[2][4][4] = {};
    float4 aR0, aR1, bR;

    aR0 = *(const float4*)(A + (m0+arow0)*D_ + ac4);
    aR1 = *(const float4*)(A + (m0+arow1)*D_ + ac4);
    bR  = *(const float4*)(Bw + (n0+brow)*D_ + bc4);

    for (int kt = 0; kt < D_; kt += 16) {
        {
            int p0 = arow0 & 3, p1 = arow1 & 3, pb = brow & 3;
            As[arow0][ac4 + (0^p0)] = splt(aR0.x);
            As[arow0][ac4 + (1^p0)] = splt(aR0.y);
            As[arow0][ac4 + (2^p0)] = splt(aR0.z);
            As[arow0][ac4 + (3^p0)] = splt(aR0.w);
            As[arow1][ac4 + (0^p1)] = splt(aR1.x);
            As[arow1][ac4 + (1^p1)] = splt(aR1.y);
            As[arow1][ac4 + (2^p1)] = splt(aR1.z);
            As[arow1][ac4 + (3^p1)] = splt(aR1.w);
            Bs[brow][bc4 + (0^pb)] = splt(bR.x);
            Bs[brow][bc4 + (1^pb)] = splt(bR.y);
            Bs[brow][bc4 + (2^pb)] = splt(bR.z);
            Bs[brow][bc4 + (3^pb)] = splt(bR.w);
        }
        __syncthreads();
        if (kt + 16 < D_) {
            aR0 = *(const float4*)(A + (m0+arow0)*D_ + kt+16 + ac4);
            aR1 = *(const float4*)(A + (m0+arow1)*D_ + kt+16 + ac4);
            bR  = *(const float4*)(Bw + (n0+brow)*D_ + kt+16 + bc4);
        }
        #pragma unroll
        for (int ks = 0; ks < 2; ks++) {
            const int k0 = ks*8 + (tg ^ sx), k1 = k0 + 4;
            unsigned aH[2][4], aL[2][4], bH[4][2], bL[4][2];
            #pragma unroll
            for (int mi = 0; mi < 2; mi++) {
                int r0 = wm*32 + mi*16 + g;
                uint2 p;
                p = As[r0  ][k0]; aH[mi][0]=p.x; aL[mi][0]=p.y;
                p = As[r0+8][k0]; aH[mi][1]=p.x; aL[mi][1]=p.y;
                p = As[r0  ][k1]; aH[mi][2]=p.x; aL[mi][2]=p.y;
                p = As[r0+8][k1]; aH[mi][3]=p.x; aL[mi][3]=p.y;
            }
            #pragma unroll
            for (int ni = 0; ni < 4; ni++) {
                int nn = wn*32 + ni*8 + g;
                uint2 p;
                p = Bs[nn][k0]; bH[ni][0]=p.x; bL[ni][0]=p.y;
                p = Bs[nn][k1]; bH[ni][1]=p.x; bL[ni][1]=p.y;
            }
            #pragma unroll
            for (int mi = 0; mi < 2; mi++)
                #pragma unroll
                for (int ni = 0; ni < 4; ni++) {
                    mma_tf32(acc[mi][ni], aH[mi], bH[ni]);
                    mma_tf32(acc[mi][ni], aH[mi], bL[ni]);
                    mma_tf32(acc[mi][ni], aL[mi], bH[ni]);
                }
        }
        __syncthreads();
    }

    #pragma unroll
    for (int mi = 0; mi < 2; mi++) {
        #pragma unroll
        for (int half = 0; half < 2; half++) {
            int r = bz*S_ + m0 + wm*32 + mi*16 + g + half*8;
            #pragma unroll
            for (int ni = 0; ni < 4; ni++) {
                int d = n0 + wn*32 + ni*8 + 2*tg;
                float2 o = make_float2(acc[mi][ni][half*2+0] + bo[d],
                                       acc[mi][ni][half*2+1] + bo[d+1]);
                *(float2*)(out + r*D_ + d) = o;
            }
        }
    }
}

// ---------------------------------------------------------------------------
extern "C" void kernel_launch(void* const* d_in, const int* in_sizes, int n_in,
                              void* d_out, int out_size)
{
    (void)in_sizes; (void)n_in; (void)out_size;
    const float* x   = (const float*)d_in[0];
    const float* wqw = (const float*)d_in[1];
    const float* wqb = (const float*)d_in[2];
    // d_in[3], d_in[4] = wk_w, wk_b : dead in reference
    const float* wvw = (const float*)d_in[5];
    const float* wvb = (const float*)d_in[6];
    const float* wow = (const float*)d_in[7];
    const float* wob = (const float*)d_in[8];
    float* out = (float*)d_out;

    qv_rope_tc<<<dim3(64, 8), 256>>>(x, wqw, wqb, wvw, wvb);
    m_kernel<<<128, 256>>>();
    w2_kernel<<<128, 256>>>(wow);
    out_tc<<<dim3(4, 8, 8), 256>>>(wob, out);
}

// round 6
// speedup vs baseline: 1.5443x; 1.5443x over previous
#include <cuda_runtime.h>

// Problem constants
#define B_ 8
#define S_ 1024
#define D_ 256
#define NR (B_*S_)   // 8192 rows

// Scratch (static device allocations — allowed)
__device__ float g_xq[NR*D_];          // rope(q)  [b,s,d]   8 MB
__device__ float g_xv[NR*D_];          // rope(v)  [b,s,d]   8 MB
__device__ float g_M [B_*16*16*16];    // M[b,h][e][f] (scaled by 1/sqrt(hd))
__device__ float g_W2[B_*D_*D_];       // per-batch effective weight, TRANSPOSED [n][k]

// ---------------------------------------------------------------------------
// 3xBF16 helpers: x = hi + lo (bf16 each, ~16 mantissa bits);
// C += Ah·Bh + Ah·Bl + Al·Bh via mma.m16n8k16.bf16 (lo·lo dropped, ~2^-18).
// ---------------------------------------------------------------------------
__device__ __forceinline__ uint2 splt2(float x0, float x1){
    unsigned hp;  // {x1_hi | x0_hi}  (first source -> upper half)
    asm("cvt.rn.bf16x2.f32 %0, %1, %2;" : "=r"(hp) : "f"(x1), "f"(x0));
    float h0 = __uint_as_float(hp << 16);
    float h1 = __uint_as_float(hp & 0xffff0000u);
    unsigned lp;
    asm("cvt.rn.bf16x2.f32 %0, %1, %2;" : "=r"(lp) : "f"(x1 - h1), "f"(x0 - h0));
    return make_uint2(hp, lp);
}
__device__ __forceinline__ void mma_bf16(float* d, const unsigned* a, const unsigned* b){
    asm volatile(
        "mma.sync.aligned.m16n8k16.row.col.f32.bf16.bf16.f32 "
        "{%0,%1,%2,%3}, {%4,%5,%6,%7}, {%8,%9}, {%0,%1,%2,%3};"
        : "+f"(d[0]), "+f"(d[1]), "+f"(d[2]), "+f"(d[3])
        : "r"(a[0]), "r"(a[1]), "r"(a[2]), "r"(a[3]),
          "r"(b[0]), "r"(b[1]));
}

// GEMM core: BM=128 BN=64 BK=16, 8 warps (4m x 2n), warp tile 32x32.
// Tiles: uint2{hi_bf16x2, lo_bf16x2} per k-PAIR; [rows][pitch 12],
// swizzle j' = j ^ (row&3). Conflict-free for stores and fragment reads.

// ---------------------------------------------------------------------------
// K1: fused Q/V projection (C = X @ W^T) + bias + RoPE -> g_xq / g_xv
// grid (64, 8): y<4 -> Q cols [y*64..), y>=4 -> V.
// ---------------------------------------------------------------------------
__global__ __launch_bounds__(256) void qv_rope_tc(
    const float* __restrict__ X,
    const float* __restrict__ Wq, const float* __restrict__ bq,
    const float* __restrict__ Wv, const float* __restrict__ bv)
{
    __shared__ __align__(16) uint2 As[128][12];
    __shared__ __align__(16) uint2 Bs[64][12];
    const int t = threadIdx.x;
    const int lane = t & 31, warp = t >> 5;
    const int g = lane >> 2, tg = lane & 3;
    const int p = g & 3;                      // read-side swizzle
    const int wm = warp & 3, wn = warp >> 2;
    const int m0 = blockIdx.x * 128;
    const bool isQ = blockIdx.y < 4;
    const int nb = (blockIdx.y & 3) * 64;
    const float* __restrict__ W    = isQ ? Wq : Wv;
    const float* __restrict__ bias = isQ ? bq : bv;
    float* __restrict__ dst        = isQ ? g_xq : g_xv;

    // Store-phase indices
    const int row0 = t >> 2;                  // 0..63
    const int row1 = row0 + 64;
    const int j0   = (t & 3) * 2;             // kpair 0,2,4,6
    const int s00 = j0 ^ (row0 & 3), s01 = (j0+1) ^ (row0 & 3);
    const int s10 = j0 ^ (row1 & 3), s11 = (j0+1) ^ (row1 & 3);
    const int cofs = (t & 3) * 4;             // float offset within k-tile

    float acc[2][4][4] = {};
    float4 aR0, aR1, bR;

    aR0 = *(const float4*)(X + (m0+row0)*D_ + cofs);
    aR1 = *(const float4*)(X + (m0+row1)*D_ + cofs);
    bR  = *(const float4*)(W + (nb+row0)*D_ + cofs);

    for (int kt = 0; kt < D_; kt += 16) {
        As[row0][s00] = splt2(aR0.x, aR0.y);
        As[row0][s01] = splt2(aR0.z, aR0.w);
        As[row1][s10] = splt2(aR1.x, aR1.y);
        As[row1][s11] = splt2(aR1.z, aR1.w);
        Bs[row0][s00] = splt2(bR.x, bR.y);
        Bs[row0][s01] = splt2(bR.z, bR.w);
        __syncthreads();
        if (kt + 16 < D_) {
            aR0 = *(const float4*)(X + (m0+row0)*D_ + kt+16 + cofs);
            aR1 = *(const float4*)(X + (m0+row1)*D_ + kt+16 + cofs);
            bR  = *(const float4*)(W + (nb+row0)*D_ + kt+16 + cofs);
        }
        {
            const int ka = tg ^ p, kb = 4 + ka;   // (tg+4)^p = 4+(tg^p)
            unsigned aH[2][4], aL[2][4], bH[4][2], bL[4][2];
            #pragma unroll
            for (int mi = 0; mi < 2; mi++) {
                int r = wm*32 + mi*16 + g;
                uint2 q;
                q = As[r  ][ka]; aH[mi][0]=q.x; aL[mi][0]=q.y;
                q = As[r+8][ka]; aH[mi][1]=q.x; aL[mi][1]=q.y;
                q = As[r  ][kb]; aH[mi][2]=q.x; aL[mi][2]=q.y;
                q = As[r+8][kb]; aH[mi][3]=q.x; aL[mi][3]=q.y;
            }
            #pragma unroll
            for (int ni = 0; ni < 4; ni++) {
                int nn = wn*32 + ni*8 + g;
                uint2 q;
                q = Bs[nn][ka]; bH[ni][0]=q.x; bL[ni][0]=q.y;
                q = Bs[nn][kb]; bH[ni][1]=q.x; bL[ni][1]=q.y;
            }
            #pragma unroll
            for (int mi = 0; mi < 2; mi++)
                #pragma unroll
                for (int ni = 0; ni < 4; ni++) {
                    mma_bf16(acc[mi][ni], aH[mi], bH[ni]);
                    mma_bf16(acc[mi][ni], aH[mi], bL[ni]);
                    mma_bf16(acc[mi][ni], aL[mi], bH[ni]);
                }
        }
        __syncthreads();
    }

    // Epilogue: bias + RoPE (theta uniform per block: nb-aligned halves).
    const float th = (nb < 128) ? 1.0f : 1e-4f;
    #pragma unroll
    for (int mi = 0; mi < 2; mi++) {
        #pragma unroll
        for (int half = 0; half < 2; half++) {
            int r = m0 + wm*32 + mi*16 + g + half*8;
            float pos = (float)((r & (S_-1)) + 1);     // 1-indexed position
            float sv, cv; sincosf(pos * th, &sv, &cv);
            #pragma unroll
            for (int ni = 0; ni < 4; ni++) {
                int d = nb + wn*32 + ni*8 + 2*tg;
                float xe = acc[mi][ni][half*2+0] + bias[d];
                float xo = acc[mi][ni][half*2+1] + bias[d+1];
                float2 o = make_float2(xe*sv - xo*cv, xe*cv + xo*sv);
                *(float2*)(dst + r*D_ + d) = o;
            }
        }
    }
}

// ---------------------------------------------------------------------------
// K2: M[b,h][e][f] = (1/sqrt(16)) * sum_s xq[b,s,16h+e]*xv[b,s,16h+f]
// ---------------------------------------------------------------------------
__global__ __launch_bounds__(256) void m_kernel()
{
    const int bh = blockIdx.x, b = bh >> 4, h = bh & 15;
    const float* __restrict__ q = g_xq + b*S_*D_ + h*16;
    const float* __restrict__ v = g_xv + b*S_*D_ + h*16;
    __shared__ __align__(16) float qs[128][20];
    __shared__ __align__(16) float vs[128][20];
    __shared__ float part[16][16][17];
    const int t = threadIdx.x;
    const int g = t >> 4, lt = t & 15;
    const int e4 = (lt >> 2) * 4, f4 = (lt & 3) * 4;
    float c[4][4] = {};

    for (int chunk = 0; chunk < 8; chunk++) {
        int sb = chunk * 128;
        #pragma unroll
        for (int i = 0; i < 2; i++) {
            int idx = t + i*256;
            int row = idx >> 2, c4 = (idx & 3) * 4;
            *(float4*)&qs[row][c4] = *(const float4*)(q + (sb+row)*D_ + c4);
            *(float4*)&vs[row][c4] = *(const float4*)(v + (sb+row)*D_ + c4);
        }
        __syncthreads();
        int r0 = g * 8;
        #pragma unroll
        for (int ss = 0; ss < 8; ss++) {
            float4 q4 = *(const float4*)&qs[r0+ss][e4];
            float4 v4 = *(const float4*)&vs[r0+ss][f4];
            c[0][0] += q4.x*v4.x; c[0][1] += q4.x*v4.y; c[0][2] += q4.x*v4.z; c[0][3] += q4.x*v4.w;
            c[1][0] += q4.y*v4.x; c[1][1] += q4.y*v4.y; c[1][2] += q4.y*v4.z; c[1][3] += q4.y*v4.w;
            c[2][0] += q4.z*v4.x; c[2][1] += q4.z*v4.y; c[2][2] += q4.z*v4.z; c[2][3] += q4.z*v4.w;
            c[3][0] += q4.w*v4.x; c[3][1] += q4.w*v4.y; c[3][2] += q4.w*v4.z; c[3][3] += q4.w*v4.w;
        }
        __syncthreads();
    }
    #pragma unroll
    for (int i = 0; i < 4; i++)
        #pragma unroll
        for (int j = 0; j < 4; j++)
            part[g][e4+i][f4+j] = c[i][j];
    __syncthreads();
    int e = t >> 4, f = t & 15;
    float s = 0.f;
    #pragma unroll
    for (int gg = 0; gg < 16; gg++) s += part[gg][e][f];
    g_M[bh*256 + t] = s * 0.25f;   // 1/sqrt(HD=16)
}

// ---------------------------------------------------------------------------
// K3: W2T[b][n][16h+e] = sum_f M[b,h][e][f] * wo[n][16h+f]   (transposed out)
// ---------------------------------------------------------------------------
__global__ __launch_bounds__(256) void w2_kernel(const float* __restrict__ Wo)
{
    const int bh = blockIdx.x, b = bh >> 4, h = bh & 15;
    __shared__ __align__(16) float wos[256][20];
    __shared__ float Ms[16][16];
    const int t = threadIdx.x;
    Ms[t >> 4][t & 15] = g_M[bh*256 + t];
    #pragma unroll
    for (int i = 0; i < 4; i++) {
        int idx = t + i*256;
        int row = idx >> 2, c4 = (idx & 3) * 4;
        *(float4*)&wos[row][c4] = *(const float4*)(Wo + row*D_ + h*16 + c4);
    }
    __syncthreads();
    const int n = t;
    float vals[16];
    #pragma unroll
    for (int e = 0; e < 16; e++) {
        float a = 0.f;
        #pragma unroll
        for (int f = 0; f < 16; f++) a += Ms[e][f] * wos[n][f];
        vals[e] = a;
    }
    float* outp = g_W2 + b*D_*D_ + n*D_ + h*16;   // [n][k] layout
    #pragma unroll
    for (int e4 = 0; e4 < 16; e4 += 4)
        *(float4*)(outp + e4) = make_float4(vals[e4], vals[e4+1], vals[e4+2], vals[e4+3]);
}

// ---------------------------------------------------------------------------
// K4: out_b = xq_b @ W2T_b^T + bo  (NT GEMM per batch, same core as K1).
// grid (4, 8, 8): x = n-block, y = m-block(128), z = batch.
// ---------------------------------------------------------------------------
__global__ __launch_bounds__(256) void out_tc(
    const float* __restrict__ bo, float* __restrict__ out)
{
    __shared__ __align__(16) uint2 As[128][12];
    __shared__ __align__(16) uint2 Bs[64][12];
    const int t = threadIdx.x;
    const int lane = t & 31, warp = t >> 5;
    const int g = lane >> 2, tg = lane & 3;
    const int p = g & 3;
    const int wm = warp & 3, wn = warp >> 2;
    const int bz = blockIdx.z;
    const int m0 = blockIdx.y * 128, n0 = blockIdx.x * 64;
    const float* __restrict__ A  = g_xq + bz*S_*D_;
    const float* __restrict__ Bw = g_W2 + bz*D_*D_;   // [n][k]

    const int row0 = t >> 2;
    const int row1 = row0 + 64;
    const int j0   = (t & 3) * 2;
    const int s00 = j0 ^ (row0 & 3), s01 = (j0+1) ^ (row0 & 3);
    const int s10 = j0 ^ (row1 & 3), s11 = (j0+1) ^ (row1 & 3);
    const int cofs = (t & 3) * 4;

    float acc[2][4][4] = {};
    float4 aR0, aR1, bR;

    aR0 = *(const float4*)(A + (m0+row0)*D_ + cofs);
    aR1 = *(const float4*)(A + (m0+row1)*D_ + cofs);
    bR  = *(const float4*)(Bw + (n0+row0)*D_ + cofs);

    for (int kt = 0; kt < D_; kt += 16) {
        As[row0][s00] = splt2(aR0.x, aR0.y);
        As[row0][s01] = splt2(aR0.z, aR0.w);
        As[row1][s10] = splt2(aR1.x, aR1.y);
        As[row1][s11] = splt2(aR1.z, aR1.w);
        Bs[row0][s00] = splt2(bR.x, bR.y);
        Bs[row0][s01] = splt2(bR.z, bR.w);
        __syncthreads();
        if (kt + 16 < D_) {
            aR0 = *(const float4*)(A + (m0+row0)*D_ + kt+16 + cofs);
            aR1 = *(const float4*)(A + (m0+row1)*D_ + kt+16 + cofs);
            bR  = *(const float4*)(Bw + (n0+row0)*D_ + kt+16 + cofs);
        }
        {
            const int ka = tg ^ p, kb = 4 + ka;
            unsigned aH[2][4], aL[2][4], bH[4][2], bL[4][2];
            #pragma unroll
            for (int mi = 0; mi < 2; mi++) {
                int r = wm*32 + mi*16 + g;
                uint2 q;
                q = As[r  ][ka]; aH[mi][0]=q.x; aL[mi][0]=q.y;
                q = As[r+8][ka]; aH[mi][1]=q.x; aL[mi][1]=q.y;
                q = As[r  ][kb]; aH[mi][2]=q.x; aL[mi][2]=q.y;
                q = As[r+8][kb]; aH[mi][3]=q.x; aL[mi][3]=q.y;
            }
            #pragma unroll
            for (int ni = 0; ni < 4; ni++) {
                int nn = wn*32 + ni*8 + g;
                uint2 q;
                q = Bs[nn][ka]; bH[ni][0]=q.x; bL[ni][0]=q.y;
                q = Bs[nn][kb]; bH[ni][1]=q.x; bL[ni][1]=q.y;
            }
            #pragma unroll
            for (int mi = 0; mi < 2; mi++)
                #pragma unroll
                for (int ni = 0; ni < 4; ni++) {
                    mma_bf16(acc[mi][ni], aH[mi], bH[ni]);
                    mma_bf16(acc[mi][ni], aH[mi], bL[ni]);
                    mma_bf16(acc[mi][ni], aL[mi], bH[ni]);
                }
        }
        __syncthreads();
    }

    #pragma unroll
    for (int mi = 0; mi < 2; mi++) {
        #pragma unroll
        for (int half = 0; half < 2; half++) {
            int r = bz*S_ + m0 + wm*32 + mi*16 + g + half*8;
            #pragma unroll
            for (int ni = 0; ni < 4; ni++) {
                int d = n0 + wn*32 + ni*8 + 2*tg;
                float2 o = make_float2(acc[mi][ni][half*2+0] + bo[d],
                                       acc[mi][ni][half*2+1] + bo[d+1]);
                *(float2*)(out + r*D_ + d) = o;
            }
        }
    }
}

// ---------------------------------------------------------------------------
extern "C" void kernel_launch(void* const* d_in, const int* in_sizes, int n_in,
                              void* d_out, int out_size)
{
    (void)in_sizes; (void)n_in; (void)out_size;
    const float* x   = (const float*)d_in[0];
    const float* wqw = (const float*)d_in[1];
    const float* wqb = (const float*)d_in[2];
    // d_in[3], d_in[4] = wk_w, wk_b : dead in reference
    const float* wvw = (const float*)d_in[5];
    const float* wvb = (const float*)d_in[6];
    const float* wow = (const float*)d_in[7];
    const float* wob = (const float*)d_in[8];
    float* out = (float*)d_out;

    qv_rope_tc<<<dim3(64, 8), 256>>>(x, wqw, wqb, wvw, wvb);
    m_kernel<<<128, 256>>>();
    w2_kernel<<<128, 256>>>(wow);
    out_tc<<<dim3(4, 8, 8), 256>>>(wob, out);
}

// round 7
// speedup vs baseline: 1.5945x; 1.0325x over previous
#include <cuda_runtime.h>

// Problem constants
#define B_ 8
#define S_ 1024
#define D_ 256
#define NR (B_*S_)   // 8192 rows

// Scratch (static device allocations — allowed)
__device__ float g_xq[NR*D_];          // rope(q)  [b,s,d]   8 MB
__device__ float g_xv[NR*D_];          // rope(v)  [b,s,d]   8 MB
__device__ float g_W2[B_*D_*D_];       // per-batch effective weight, TRANSPOSED [n][k]

// ---------------------------------------------------------------------------
// 3xBF16 helpers: x = hi + lo (bf16 each, ~16 mantissa bits);
// C += Ah·Bh + Ah·Bl + Al·Bh via mma.m16n8k16.bf16 (lo·lo dropped, ~2^-18).
// ---------------------------------------------------------------------------
__device__ __forceinline__ uint2 splt2(float x0, float x1){
    unsigned hp;  // {x1_hi | x0_hi}
    asm("cvt.rn.bf16x2.f32 %0, %1, %2;" : "=r"(hp) : "f"(x1), "f"(x0));
    float h0 = __uint_as_float(hp << 16);
    float h1 = __uint_as_float(hp & 0xffff0000u);
    unsigned lp;
    asm("cvt.rn.bf16x2.f32 %0, %1, %2;" : "=r"(lp) : "f"(x1 - h1), "f"(x0 - h0));
    return make_uint2(hp, lp);
}
__device__ __forceinline__ void mma_bf16(float* d, const unsigned* a, const unsigned* b){
    asm volatile(
        "mma.sync.aligned.m16n8k16.row.col.f32.bf16.bf16.f32 "
        "{%0,%1,%2,%3}, {%4,%5,%6,%7}, {%8,%9}, {%0,%1,%2,%3};"
        : "+f"(d[0]), "+f"(d[1]), "+f"(d[2]), "+f"(d[3])
        : "r"(a[0]), "r"(a[1]), "r"(a[2]), "r"(a[3]),
          "r"(b[0]), "r"(b[1]));
}

// GEMM core: BM=128 BN=64 BK=16, 8 warps (4m x 2n), warp tile 32x32.
// Tiles: uint2{hi_bf16x2, lo_bf16x2} per k-PAIR; [buf][rows][pitch 12],
// swizzle j' = j ^ (row&3). Double-buffered: 1 sync/iter; stores at iter i
// hit the buffer computed at iter i-1 (protected by that iter's barrier).

#define GEMM_COMPUTE(ASrc, BSrc)                                              \
    {                                                                         \
        const int ka = tg ^ pswz, kb = 4 + ka;                                \
        unsigned aH[2][4], aL[2][4], bH[4][2], bL[4][2];                      \
        _Pragma("unroll")                                                     \
        for (int mi = 0; mi < 2; mi++) {                                      \
            int r = wm*32 + mi*16 + g;                                        \
            uint2 q;                                                          \
            q = ASrc[r  ][ka]; aH[mi][0]=q.x; aL[mi][0]=q.y;                  \
            q = ASrc[r+8][ka]; aH[mi][1]=q.x; aL[mi][1]=q.y;                  \
            q = ASrc[r  ][kb]; aH[mi][2]=q.x; aL[mi][2]=q.y;                  \
            q = ASrc[r+8][kb]; aH[mi][3]=q.x; aL[mi][3]=q.y;                  \
        }                                                                     \
        _Pragma("unroll")                                                     \
        for (int ni = 0; ni < 4; ni++) {                                      \
            int nn = wn*32 + ni*8 + g;                                        \
            uint2 q;                                                          \
            q = BSrc[nn][ka]; bH[ni][0]=q.x; bL[ni][0]=q.y;                   \
            q = BSrc[nn][kb]; bH[ni][1]=q.x; bL[ni][1]=q.y;                   \
        }                                                                     \
        _Pragma("unroll")                                                     \
        for (int mi = 0; mi < 2; mi++)                                        \
            _Pragma("unroll")                                                 \
            for (int ni = 0; ni < 4; ni++) {                                  \
                mma_bf16(acc[mi][ni], aH[mi], bH[ni]);                        \
                mma_bf16(acc[mi][ni], aH[mi], bL[ni]);                        \
                mma_bf16(acc[mi][ni], aL[mi], bH[ni]);                        \
            }                                                                 \
    }

#define GEMM_STORE(ADst, BDst)                                                \
    {                                                                         \
        ADst[row0][s00] = splt2(aR0.x, aR0.y);                                \
        ADst[row0][s01] = splt2(aR0.z, aR0.w);                                \
        ADst[row1][s10] = splt2(aR1.x, aR1.y);                                \
        ADst[row1][s11] = splt2(aR1.z, aR1.w);                                \
        BDst[row0][s00] = splt2(bR.x, bR.y);                                  \
        BDst[row0][s01] = splt2(bR.z, bR.w);                                  \
    }

// ---------------------------------------------------------------------------
// K1: fused Q/V projection (C = X @ W^T) + bias + RoPE -> g_xq / g_xv
// grid (64, 8): y<4 -> Q cols [y*64..), y>=4 -> V.
// ---------------------------------------------------------------------------
__global__ __launch_bounds__(256) void qv_rope_tc(
    const float* __restrict__ X,
    const float* __restrict__ Wq, const float* __restrict__ bq,
    const float* __restrict__ Wv, const float* __restrict__ bv)
{
    __shared__ __align__(16) uint2 As[2][128][12];
    __shared__ __align__(16) uint2 Bs[2][64][12];
    const int t = threadIdx.x;
    const int lane = t & 31, warp = t >> 5;
    const int g = lane >> 2, tg = lane & 3;
    const int pswz = g & 3;
    const int wm = warp & 3, wn = warp >> 2;
    const int m0 = blockIdx.x * 128;
    const bool isQ = blockIdx.y < 4;
    const int nb = (blockIdx.y & 3) * 64;
    const float* __restrict__ W    = isQ ? Wq : Wv;
    const float* __restrict__ bias = isQ ? bq : bv;
    float* __restrict__ dst        = isQ ? g_xq : g_xv;

    const int row0 = t >> 2;                  // 0..63
    const int row1 = row0 + 64;
    const int j0   = (t & 3) * 2;
    const int s00 = j0 ^ (row0 & 3), s01 = (j0+1) ^ (row0 & 3);
    const int s10 = j0 ^ (row1 & 3), s11 = (j0+1) ^ (row1 & 3);
    const int cofs = (t & 3) * 4;

    float acc[2][4][4] = {};
    float4 aR0, aR1, bR;

    aR0 = *(const float4*)(X + (m0+row0)*D_ + cofs);
    aR1 = *(const float4*)(X + (m0+row1)*D_ + cofs);
    bR  = *(const float4*)(W + (nb+row0)*D_ + cofs);
    GEMM_STORE(As[0], Bs[0]);
    __syncthreads();

    #pragma unroll
    for (int it = 0; it < 16; it++) {
        const int cur = it & 1;
        if (it < 15) {
            int kt = (it+1) * 16;
            aR0 = *(const float4*)(X + (m0+row0)*D_ + kt + cofs);
            aR1 = *(const float4*)(X + (m0+row1)*D_ + kt + cofs);
            bR  = *(const float4*)(W + (nb+row0)*D_ + kt + cofs);
        }
        GEMM_COMPUTE(As[cur], Bs[cur]);
        if (it < 15) GEMM_STORE(As[1-cur], Bs[1-cur]);
        __syncthreads();
    }

    // Epilogue: bias + RoPE (theta uniform per block: nb-aligned halves).
    const float th = (nb < 128) ? 1.0f : 1e-4f;
    #pragma unroll
    for (int mi = 0; mi < 2; mi++) {
        #pragma unroll
        for (int half = 0; half < 2; half++) {
            int r = m0 + wm*32 + mi*16 + g + half*8;
            float pos = (float)((r & (S_-1)) + 1);     // 1-indexed position
            float sv, cv; sincosf(pos * th, &sv, &cv);
            #pragma unroll
            for (int ni = 0; ni < 4; ni++) {
                int d = nb + wn*32 + ni*8 + 2*tg;
                float xe = acc[mi][ni][half*2+0] + bias[d];
                float xo = acc[mi][ni][half*2+1] + bias[d+1];
                float2 o = make_float2(xe*sv - xo*cv, xe*cv + xo*sv);
                *(float2*)(dst + r*D_ + d) = o;
            }
        }
    }
}

// ---------------------------------------------------------------------------
// K2 (fused): per (b,h): M[e][f] = (1/4) * sum_s xq[..e]*xv[..f]  (in smem),
// then W2T[b][n][16h+e] = sum_f M[e][f] * wo[n][16h+f].
// smem union: phase1 {qs, vs, part} / phase2 {wos}; Ms persists.
// ---------------------------------------------------------------------------
__global__ __launch_bounds__(256) void mw_kernel(const float* __restrict__ Wo)
{
    __shared__ __align__(16) char smem_raw[38912];
    float (*qs)[20]       = (float(*)[20])(smem_raw);            // 128*20*4 = 10240
    float (*vs)[20]       = (float(*)[20])(smem_raw + 10240);    // 10240
    float (*part)[16][17] = (float(*)[16][17])(smem_raw + 20480);// 16*16*17*4 = 17408
    float (*wos)[20]      = (float(*)[20])(smem_raw);            // phase2: 256*20*4 = 20480
    __shared__ float Ms[16][16];

    const int bh = blockIdx.x, b = bh >> 4, h = bh & 15;
    const float* __restrict__ q = g_xq + b*S_*D_ + h*16;
    const float* __restrict__ v = g_xv + b*S_*D_ + h*16;
    const int t = threadIdx.x;
    const int grp = t >> 4, lt = t & 15;
    const int e4 = (lt >> 2) * 4, f4 = (lt & 3) * 4;
    float c[4][4] = {};

    for (int chunk = 0; chunk < 8; chunk++) {
        int sb = chunk * 128;
        #pragma unroll
        for (int i = 0; i < 2; i++) {
            int idx = t + i*256;
            int row = idx >> 2, c4 = (idx & 3) * 4;
            *(float4*)&qs[row][c4] = *(const float4*)(q + (sb+row)*D_ + c4);
            *(float4*)&vs[row][c4] = *(const float4*)(v + (sb+row)*D_ + c4);
        }
        __syncthreads();
        int r0 = grp * 8;
        #pragma unroll
        for (int ss = 0; ss < 8; ss++) {
            float4 q4 = *(const float4*)&qs[r0+ss][e4];
            float4 v4 = *(const float4*)&vs[r0+ss][f4];
            c[0][0] += q4.x*v4.x; c[0][1] += q4.x*v4.y; c[0][2] += q4.x*v4.z; c[0][3] += q4.x*v4.w;
            c[1][0] += q4.y*v4.x; c[1][1] += q4.y*v4.y; c[1][2] += q4.y*v4.z; c[1][3] += q4.y*v4.w;
            c[2][0] += q4.z*v4.x; c[2][1] += q4.z*v4.y; c[2][2] += q4.z*v4.z; c[2][3] += q4.z*v4.w;
            c[3][0] += q4.w*v4.x; c[3][1] += q4.w*v4.y; c[3][2] += q4.w*v4.z; c[3][3] += q4.w*v4.w;
        }
        __syncthreads();
    }
    #pragma unroll
    for (int i = 0; i < 4; i++)
        #pragma unroll
        for (int j = 0; j < 4; j++)
            part[grp][e4+i][f4+j] = c[i][j];
    __syncthreads();
    {
        int e = t >> 4, f = t & 15;
        float s = 0.f;
        #pragma unroll
        for (int gg = 0; gg < 16; gg++) s += part[gg][e][f];
        __syncthreads();                 // all part reads done before wos overwrite
        Ms[e][f] = s * 0.25f;            // 1/sqrt(HD=16)
    }
    // phase 2: load wo columns [h*16, h*16+16) for all 256 rows
    #pragma unroll
    for (int i = 0; i < 4; i++) {
        int idx = t + i*256;
        int row = idx >> 2, c4 = (idx & 3) * 4;
        *(float4*)&wos[row][c4] = *(const float4*)(Wo + row*D_ + h*16 + c4);
    }
    __syncthreads();
    const int n = t;
    float vals[16];
    #pragma unroll
    for (int e = 0; e < 16; e++) {
        float a = 0.f;
        #pragma unroll
        for (int f = 0; f < 16; f++) a += Ms[e][f] * wos[n][f];
        vals[e] = a;
    }
    float* outp = g_W2 + b*D_*D_ + n*D_ + h*16;   // [n][k] layout
    #pragma unroll
    for (int e4o = 0; e4o < 16; e4o += 4)
        *(float4*)(outp + e4o) = make_float4(vals[e4o], vals[e4o+1], vals[e4o+2], vals[e4o+3]);
}

// ---------------------------------------------------------------------------
// K3: out_b = xq_b @ W2T_b^T + bo  (NT GEMM per batch, same core as K1).
// grid (4, 8, 8): x = n-block, y = m-block(128), z = batch.
// ---------------------------------------------------------------------------
__global__ __launch_bounds__(256) void out_tc(
    const float* __restrict__ bo, float* __restrict__ out)
{
    __shared__ __align__(16) uint2 As[2][128][12];
    __shared__ __align__(16) uint2 Bs[2][64][12];
    const int t = threadIdx.x;
    const int lane = t & 31, warp = t >> 5;
    const int g = lane >> 2, tg = lane & 3;
    const int pswz = g & 3;
    const int wm = warp & 3, wn = warp >> 2;
    const int bz = blockIdx.z;
    const int m0 = blockIdx.y * 128, n0 = blockIdx.x * 64;
    const float* __restrict__ A  = g_xq + bz*S_*D_;
    const float* __restrict__ Bw = g_W2 + bz*D_*D_;   // [n][k]

    const int row0 = t >> 2;
    const int row1 = row0 + 64;
    const int j0   = (t & 3) * 2;
    const int s00 = j0 ^ (row0 & 3), s01 = (j0+1) ^ (row0 & 3);
    const int s10 = j0 ^ (row1 & 3), s11 = (j0+1) ^ (row1 & 3);
    const int cofs = (t & 3) * 4;

    float acc[2][4][4] = {};
    float4 aR0, aR1, bR;

    aR0 = *(const float4*)(A + (m0+row0)*D_ + cofs);
    aR1 = *(const float4*)(A + (m0+row1)*D_ + cofs);
    bR  = *(const float4*)(Bw + (n0+row0)*D_ + cofs);
    GEMM_STORE(As[0], Bs[0]);
    __syncthreads();

    #pragma unroll
    for (int it = 0; it < 16; it++) {
        const int cur = it & 1;
        if (it < 15) {
            int kt = (it+1) * 16;
            aR0 = *(const float4*)(A + (m0+row0)*D_ + kt + cofs);
            aR1 = *(const float4*)(A + (m0+row1)*D_ + kt + cofs);
            bR  = *(const float4*)(Bw + (n0+row0)*D_ + kt + cofs);
        }
        GEMM_COMPUTE(As[cur], Bs[cur]);
        if (it < 15) GEMM_STORE(As[1-cur], Bs[1-cur]);
        __syncthreads();
    }

    #pragma unroll
    for (int mi = 0; mi < 2; mi++) {
        #pragma unroll
        for (int half = 0; half < 2; half++) {
            int r = bz*S_ + m0 + wm*32 + mi*16 + g + half*8;
            #pragma unroll
            for (int ni = 0; ni < 4; ni++) {
                int d = n0 + wn*32 + ni*8 + 2*tg;
                float2 o = make_float2(acc[mi][ni][half*2+0] + bo[d],
                                       acc[mi][ni][half*2+1] + bo[d+1]);
                *(float2*)(out + r*D_ + d) = o;
            }
        }
    }
}

// ---------------------------------------------------------------------------
extern "C" void kernel_launch(void* const* d_in, const int* in_sizes, int n_in,
                              void* d_out, int out_size)
{
    (void)in_sizes; (void)n_in; (void)out_size;
    const float* x   = (const float*)d_in[0];
    const float* wqw = (const float*)d_in[1];
    const float* wqb = (const float*)d_in[2];
    // d_in[3], d_in[4] = wk_w, wk_b : dead in reference
    const float* wvw = (const float*)d_in[5];
    const float* wvb = (const float*)d_in[6];
    const float* wow = (const float*)d_in[7];
    const float* wob = (const float*)d_in[8];
    float* out = (float*)d_out;

    qv_rope_tc<<<dim3(64, 8), 256>>>(x, wqw, wqb, wvw, wvb);
    mw_kernel<<<128, 256>>>(wow);
    out_tc<<<dim3(4, 8, 8), 256>>>(wob, out);
}

// round 8
// speedup vs baseline: 1.6650x; 1.0442x over previous
#include <cuda_runtime.h>

// Problem constants
#define B_ 8
#define S_ 1024
#define D_ 256
#define NR (B_*S_)   // 8192 rows

// Scratch (static device allocations — allowed)
__device__ float g_xq[NR*D_];          // rope(q)  [b,s,d]   8 MB
__device__ float g_xv[NR*D_];          // rope(v)  [b,s,d]   8 MB
__device__ float g_W2[B_*D_*D_];       // per-batch effective weight, TRANSPOSED [n][k]

// ---------------------------------------------------------------------------
// 3xBF16 helpers: x = hi + lo (bf16 each, ~16 mantissa bits);
// C += Ah·Bh + Ah·Bl + Al·Bh via mma.m16n8k16.bf16 (lo·lo dropped, ~2^-18).
// ---------------------------------------------------------------------------
__device__ __forceinline__ uint2 splt2(float x0, float x1){
    unsigned hp;  // {x1_hi | x0_hi}
    asm("cvt.rn.bf16x2.f32 %0, %1, %2;" : "=r"(hp) : "f"(x1), "f"(x0));
    float h0 = __uint_as_float(hp << 16);
    float h1 = __uint_as_float(hp & 0xffff0000u);
    unsigned lp;
    asm("cvt.rn.bf16x2.f32 %0, %1, %2;" : "=r"(lp) : "f"(x1 - h1), "f"(x0 - h0));
    return make_uint2(hp, lp);
}
__device__ __forceinline__ void mma_bf16(float* d, const unsigned* a, const unsigned* b){
    asm volatile(
        "mma.sync.aligned.m16n8k16.row.col.f32.bf16.bf16.f32 "
        "{%0,%1,%2,%3}, {%4,%5,%6,%7}, {%8,%9}, {%0,%1,%2,%3};"
        : "+f"(d[0]), "+f"(d[1]), "+f"(d[2]), "+f"(d[3])
        : "r"(a[0]), "r"(a[1]), "r"(a[2]), "r"(a[3]),
          "r"(b[0]), "r"(b[1]));
}

// Tiles: uint2{hi_bf16x2, lo_bf16x2} per k-PAIR; [buf][rows][pitch 12],
// swizzle j' = j ^ (row&3). Conflict-free for stores and fragment reads.
// Double-buffered: 1 sync/iter.

// ---------------------------------------------------------------------------
// K1: fused Q+V projection (Cq = X Wq^T, Cv = X Wv^T) + bias + RoPE.
// BM=128 BN=64 BK=16; A tile shared by both B tiles -> 48 MMA per A-frag set.
// grid (64, 4): x = m-block, y = n-block. 8 warps (4m x 2n), warp tile 32x32.
// ---------------------------------------------------------------------------
__global__ __launch_bounds__(256, 2) void qv2_tc(
    const float* __restrict__ X,
    const float* __restrict__ Wq, const float* __restrict__ bq,
    const float* __restrict__ Wv, const float* __restrict__ bv)
{
    __shared__ __align__(16) uint2 As[2][128][12];   // 24 KB
    __shared__ __align__(16) uint2 Bq[2][64][12];    // 12 KB
    __shared__ __align__(16) uint2 Bv[2][64][12];    // 12 KB
    const int t = threadIdx.x;
    const int lane = t & 31, warp = t >> 5;
    const int g = lane >> 2, tg = lane & 3;
    const int pswz = g & 3;
    const int wm = warp & 3, wn = warp >> 2;
    const int m0 = blockIdx.x * 128;
    const int nb = blockIdx.y * 64;

    const int row0 = t >> 2;                  // 0..63
    const int row1 = row0 + 64;
    const int j0   = (t & 3) * 2;
    const int s00 = j0 ^ (row0 & 3), s01 = (j0+1) ^ (row0 & 3);
    const int s10 = j0 ^ (row1 & 3), s11 = (j0+1) ^ (row1 & 3);
    const int cofs = (t & 3) * 4;

    float accQ[2][4][4] = {};
    float accV[2][4][4] = {};
    float4 aR0, aR1, qR, vR;

    aR0 = *(const float4*)(X  + (m0+row0)*D_ + cofs);
    aR1 = *(const float4*)(X  + (m0+row1)*D_ + cofs);
    qR  = *(const float4*)(Wq + (nb+row0)*D_ + cofs);
    vR  = *(const float4*)(Wv + (nb+row0)*D_ + cofs);

    #define QV_STORE(buf)                                  \
        As[buf][row0][s00] = splt2(aR0.x, aR0.y);          \
        As[buf][row0][s01] = splt2(aR0.z, aR0.w);          \
        As[buf][row1][s10] = splt2(aR1.x, aR1.y);          \
        As[buf][row1][s11] = splt2(aR1.z, aR1.w);          \
        Bq[buf][row0][s00] = splt2(qR.x, qR.y);            \
        Bq[buf][row0][s01] = splt2(qR.z, qR.w);            \
        Bv[buf][row0][s00] = splt2(vR.x, vR.y);            \
        Bv[buf][row0][s01] = splt2(vR.z, vR.w);

    QV_STORE(0);
    __syncthreads();

    #pragma unroll
    for (int it = 0; it < 16; it++) {
        const int cur = it & 1;
        if (it < 15) {
            int kt = (it+1) * 16;
            aR0 = *(const float4*)(X  + (m0+row0)*D_ + kt + cofs);
            aR1 = *(const float4*)(X  + (m0+row1)*D_ + kt + cofs);
            qR  = *(const float4*)(Wq + (nb+row0)*D_ + kt + cofs);
            vR  = *(const float4*)(Wv + (nb+row0)*D_ + kt + cofs);
        }
        {
            const int ka = tg ^ pswz, kb2 = 4 + ka;
            unsigned aH[2][4], aL[2][4], bH[4][2], bL[4][2];
            #pragma unroll
            for (int mi = 0; mi < 2; mi++) {
                int r = wm*32 + mi*16 + g;
                uint2 q;
                q = As[cur][r  ][ka];  aH[mi][0]=q.x; aL[mi][0]=q.y;
                q = As[cur][r+8][ka];  aH[mi][1]=q.x; aL[mi][1]=q.y;
                q = As[cur][r  ][kb2]; aH[mi][2]=q.x; aL[mi][2]=q.y;
                q = As[cur][r+8][kb2]; aH[mi][3]=q.x; aL[mi][3]=q.y;
            }
            // Q half
            #pragma unroll
            for (int ni = 0; ni < 4; ni++) {
                int nn = wn*32 + ni*8 + g;
                uint2 q;
                q = Bq[cur][nn][ka];  bH[ni][0]=q.x; bL[ni][0]=q.y;
                q = Bq[cur][nn][kb2]; bH[ni][1]=q.x; bL[ni][1]=q.y;
            }
            #pragma unroll
            for (int mi = 0; mi < 2; mi++)
                #pragma unroll
                for (int ni = 0; ni < 4; ni++) {
                    mma_bf16(accQ[mi][ni], aH[mi], bH[ni]);
                    mma_bf16(accQ[mi][ni], aH[mi], bL[ni]);
                    mma_bf16(accQ[mi][ni], aL[mi], bH[ni]);
                }
            // V half (reuse bH/bL)
            #pragma unroll
            for (int ni = 0; ni < 4; ni++) {
                int nn = wn*32 + ni*8 + g;
                uint2 q;
                q = Bv[cur][nn][ka];  bH[ni][0]=q.x; bL[ni][0]=q.y;
                q = Bv[cur][nn][kb2]; bH[ni][1]=q.x; bL[ni][1]=q.y;
            }
            #pragma unroll
            for (int mi = 0; mi < 2; mi++)
                #pragma unroll
                for (int ni = 0; ni < 4; ni++) {
                    mma_bf16(accV[mi][ni], aH[mi], bH[ni]);
                    mma_bf16(accV[mi][ni], aH[mi], bL[ni]);
                    mma_bf16(accV[mi][ni], aL[mi], bH[ni]);
                }
        }
        if (it < 15) { QV_STORE(1 - (it & 1)); }
        __syncthreads();
    }
    #undef QV_STORE

    // Epilogue: bias + RoPE (theta uniform per block: nb-aligned halves).
    const float th = (nb < 128) ? 1.0f : 1e-4f;
    #pragma unroll
    for (int mi = 0; mi < 2; mi++) {
        #pragma unroll
        for (int half = 0; half < 2; half++) {
            int r = m0 + wm*32 + mi*16 + g + half*8;
            float pos = (float)((r & (S_-1)) + 1);     // 1-indexed position
            float sv, cv; sincosf(pos * th, &sv, &cv);
            #pragma unroll
            for (int ni = 0; ni < 4; ni++) {
                int d = nb + wn*32 + ni*8 + 2*tg;
                float xe, xo;
                xe = accQ[mi][ni][half*2+0] + bq[d];
                xo = accQ[mi][ni][half*2+1] + bq[d+1];
                *(float2*)(g_xq + r*D_ + d) = make_float2(xe*sv - xo*cv, xe*cv + xo*sv);
                xe = accV[mi][ni][half*2+0] + bv[d];
                xo = accV[mi][ni][half*2+1] + bv[d+1];
                *(float2*)(g_xv + r*D_ + d) = make_float2(xe*sv - xo*cv, xe*cv + xo*sv);
            }
        }
    }
}

// ---------------------------------------------------------------------------
// K2 (fused): per (b,h): M[e][f] = (1/4) * sum_s xq[..e]*xv[..f]  (in smem),
// then W2T[b][n][16h+e] = sum_f M[e][f] * wo[n][16h+f].
// ---------------------------------------------------------------------------
__global__ __launch_bounds__(256) void mw_kernel(const float* __restrict__ Wo)
{
    __shared__ __align__(16) char smem_raw[38912];
    float (*qs)[20]       = (float(*)[20])(smem_raw);            // 10240
    float (*vs)[20]       = (float(*)[20])(smem_raw + 10240);    // 10240
    float (*part)[16][17] = (float(*)[16][17])(smem_raw + 20480);// 17408
    float (*wos)[20]      = (float(*)[20])(smem_raw);            // phase2: 20480
    __shared__ float Ms[16][16];

    const int bh = blockIdx.x, b = bh >> 4, h = bh & 15;
    const float* __restrict__ q = g_xq + b*S_*D_ + h*16;
    const float* __restrict__ v = g_xv + b*S_*D_ + h*16;
    const int t = threadIdx.x;
    const int grp = t >> 4, lt = t & 15;
    const int e4 = (lt >> 2) * 4, f4 = (lt & 3) * 4;
    float c[4][4] = {};

    for (int chunk = 0; chunk < 8; chunk++) {
        int sb = chunk * 128;
        #pragma unroll
        for (int i = 0; i < 2; i++) {
            int idx = t + i*256;
            int row = idx >> 2, c4 = (idx & 3) * 4;
            *(float4*)&qs[row][c4] = *(const float4*)(q + (sb+row)*D_ + c4);
            *(float4*)&vs[row][c4] = *(const float4*)(v + (sb+row)*D_ + c4);
        }
        __syncthreads();
        int r0 = grp * 8;
        #pragma unroll
        for (int ss = 0; ss < 8; ss++) {
            float4 q4 = *(const float4*)&qs[r0+ss][e4];
            float4 v4 = *(const float4*)&vs[r0+ss][f4];
            c[0][0] += q4.x*v4.x; c[0][1] += q4.x*v4.y; c[0][2] += q4.x*v4.z; c[0][3] += q4.x*v4.w;
            c[1][0] += q4.y*v4.x; c[1][1] += q4.y*v4.y; c[1][2] += q4.y*v4.z; c[1][3] += q4.y*v4.w;
            c[2][0] += q4.z*v4.x; c[2][1] += q4.z*v4.y; c[2][2] += q4.z*v4.z; c[2][3] += q4.z*v4.w;
            c[3][0] += q4.w*v4.x; c[3][1] += q4.w*v4.y; c[3][2] += q4.w*v4.z; c[3][3] += q4.w*v4.w;
        }
        __syncthreads();
    }
    #pragma unroll
    for (int i = 0; i < 4; i++)
        #pragma unroll
        for (int j = 0; j < 4; j++)
            part[grp][e4+i][f4+j] = c[i][j];
    __syncthreads();
    {
        int e = t >> 4, f = t & 15;
        float s = 0.f;
        #pragma unroll
        for (int gg = 0; gg < 16; gg++) s += part[gg][e][f];
        __syncthreads();                 // all part reads done before wos overwrite
        Ms[e][f] = s * 0.25f;            // 1/sqrt(HD=16)
    }
    #pragma unroll
    for (int i = 0; i < 4; i++) {
        int idx = t + i*256;
        int row = idx >> 2, c4 = (idx & 3) * 4;
        *(float4*)&wos[row][c4] = *(const float4*)(Wo + row*D_ + h*16 + c4);
    }
    __syncthreads();
    const int n = t;
    float vals[16];
    #pragma unroll
    for (int e = 0; e < 16; e++) {
        float a = 0.f;
        #pragma unroll
        for (int f = 0; f < 16; f++) a += Ms[e][f] * wos[n][f];
        vals[e] = a;
    }
    float* outp = g_W2 + b*D_*D_ + n*D_ + h*16;   // [n][k] layout
    #pragma unroll
    for (int e4o = 0; e4o < 16; e4o += 4)
        *(float4*)(outp + e4o) = make_float4(vals[e4o], vals[e4o+1], vals[e4o+2], vals[e4o+3]);
}

// ---------------------------------------------------------------------------
// K3: out_b = xq_b @ W2T_b^T + bo  (NT GEMM per batch).
// BM=128 BN=128 BK=16; 8 warps (4m x 2n), warp tile 32x64.
// grid (2, 8, 8): x = n-block, y = m-block, z = batch.
// ---------------------------------------------------------------------------
__global__ __launch_bounds__(256, 2) void out_tc(
    const float* __restrict__ bo, float* __restrict__ out)
{
    __shared__ __align__(16) uint2 As[2][128][12];   // 24 KB
    __shared__ __align__(16) uint2 Bs[2][128][12];   // 24 KB
    const int t = threadIdx.x;
    const int lane = t & 31, warp = t >> 5;
    const int g = lane >> 2, tg = lane & 3;
    const int pswz = g & 3;
    const int wm = warp & 3, wn = warp >> 2;
    const int bz = blockIdx.z;
    const int m0 = blockIdx.y * 128, n0 = blockIdx.x * 128;
    const float* __restrict__ A  = g_xq + bz*S_*D_;
    const float* __restrict__ Bw = g_W2 + bz*D_*D_;   // [n][k]

    const int row0 = t >> 2;
    const int row1 = row0 + 64;
    const int j0   = (t & 3) * 2;
    const int s00 = j0 ^ (row0 & 3), s01 = (j0+1) ^ (row0 & 3);
    const int s10 = j0 ^ (row1 & 3), s11 = (j0+1) ^ (row1 & 3);
    const int cofs = (t & 3) * 4;

    float acc[2][8][4] = {};
    float4 aR0, aR1, bR0, bR1;

    aR0 = *(const float4*)(A  + (m0+row0)*D_ + cofs);
    aR1 = *(const float4*)(A  + (m0+row1)*D_ + cofs);
    bR0 = *(const float4*)(Bw + (n0+row0)*D_ + cofs);
    bR1 = *(const float4*)(Bw + (n0+row1)*D_ + cofs);

    #define OUT_STORE(buf)                                 \
        As[buf][row0][s00] = splt2(aR0.x, aR0.y);          \
        As[buf][row0][s01] = splt2(aR0.z, aR0.w);          \
        As[buf][row1][s10] = splt2(aR1.x, aR1.y);          \
        As[buf][row1][s11] = splt2(aR1.z, aR1.w);          \
        Bs[buf][row0][s00] = splt2(bR0.x, bR0.y);          \
        Bs[buf][row0][s01] = splt2(bR0.z, bR0.w);          \
        Bs[buf][row1][s10] = splt2(bR1.x, bR1.y);          \
        Bs[buf][row1][s11] = splt2(bR1.z, bR1.w);

    OUT_STORE(0);
    __syncthreads();

    #pragma unroll
    for (int it = 0; it < 16; it++) {
        const int cur = it & 1;
        if (it < 15) {
            int kt = (it+1) * 16;
            aR0 = *(const float4*)(A  + (m0+row0)*D_ + kt + cofs);
            aR1 = *(const float4*)(A  + (m0+row1)*D_ + kt + cofs);
            bR0 = *(const float4*)(Bw + (n0+row0)*D_ + kt + cofs);
            bR1 = *(const float4*)(Bw + (n0+row1)*D_ + kt + cofs);
        }
        {
            const int ka = tg ^ pswz, kb2 = 4 + ka;
            unsigned aH[2][4], aL[2][4], bH[4][2], bL[4][2];
            #pragma unroll
            for (int mi = 0; mi < 2; mi++) {
                int r = wm*32 + mi*16 + g;
                uint2 q;
                q = As[cur][r  ][ka];  aH[mi][0]=q.x; aL[mi][0]=q.y;
                q = As[cur][r+8][ka];  aH[mi][1]=q.x; aL[mi][1]=q.y;
                q = As[cur][r  ][kb2]; aH[mi][2]=q.x; aL[mi][2]=q.y;
                q = As[cur][r+8][kb2]; aH[mi][3]=q.x; aL[mi][3]=q.y;
            }
            #pragma unroll
            for (int nh = 0; nh < 2; nh++) {
                #pragma unroll
                for (int ni = 0; ni < 4; ni++) {
                    int nn = wn*64 + (nh*4+ni)*8 + g;
                    uint2 q;
                    q = Bs[cur][nn][ka];  bH[ni][0]=q.x; bL[ni][0]=q.y;
                    q = Bs[cur][nn][kb2]; bH[ni][1]=q.x; bL[ni][1]=q.y;
                }
                #pragma unroll
                for (int mi = 0; mi < 2; mi++)
                    #pragma unroll
                    for (int ni = 0; ni < 4; ni++) {
                        mma_bf16(acc[mi][nh*4+ni], aH[mi], bH[ni]);
                        mma_bf16(acc[mi][nh*4+ni], aH[mi], bL[ni]);
                        mma_bf16(acc[mi][nh*4+ni], aL[mi], bH[ni]);
                    }
            }
        }
        if (it < 15) { OUT_STORE(1 - (it & 1)); }
        __syncthreads();
    }
    #undef OUT_STORE

    #pragma unroll
    for (int mi = 0; mi < 2; mi++) {
        #pragma unroll
        for (int half = 0; half < 2; half++) {
            int r = bz*S_ + m0 + wm*32 + mi*16 + g + half*8;
            #pragma unroll
            for (int ni = 0; ni < 8; ni++) {
                int d = n0 + wn*64 + ni*8 + 2*tg;
                float2 o = make_float2(acc[mi][ni][half*2+0] + bo[d],
                                       acc[mi][ni][half*2+1] + bo[d+1]);
                *(float2*)(out + r*D_ + d) = o;
            }
        }
    }
}

// ---------------------------------------------------------------------------
extern "C" void kernel_launch(void* const* d_in, const int* in_sizes, int n_in,
                              void* d_out, int out_size)
{
    (void)in_sizes; (void)n_in; (void)out_size;
    const float* x   = (const float*)d_in[0];
    const float* wqw = (const float*)d_in[1];
    const float* wqb = (const float*)d_in[2];
    // d_in[3], d_in[4] = wk_w, wk_b : dead in reference
    const float* wvw = (const float*)d_in[5];
    const float* wvb = (const float*)d_in[6];
    const float* wow = (const float*)d_in[7];
    const float* wob = (const float*)d_in[8];
    float* out = (float*)d_out;

    qv2_tc<<<dim3(64, 4), 256>>>(x, wqw, wqb, wvw, wvb);
    mw_kernel<<<128, 256>>>(wow);
    out_tc<<<dim3(2, 8, 8), 256>>>(wob, out);
}

// round 9
// speedup vs baseline: 1.7084x; 1.0260x over previous
#include <cuda_runtime.h>

// Problem constants
#define B_ 8
#define S_ 1024
#define D_ 256
#define NR (B_*S_)   // 8192 rows

// Scratch (static device allocations — allowed)
__device__ float g_xq[NR*D_];                       // rope(q) f32 (for mw)
__device__ float g_xv[NR*D_];                       // rope(v) f32 (for mw)
__device__ __align__(16) uint2 g_xs [NR*128];       // X   split {hi,lo} per pair
__device__ __align__(16) uint2 g_wqs[D_*128];       // Wq  split
__device__ __align__(16) uint2 g_wvs[D_*128];       // Wv  split
__device__ __align__(16) uint2 g_xqs[NR*128];       // rope(q) split (for out)
__device__ __align__(16) uint2 g_w2s[B_*D_*128];    // W2^T split [b][n][kpair]

// ---------------------------------------------------------------------------
// 3xBF16: x = hi + lo (bf16 each); C += Ah·Bh + Ah·Bl + Al·Bh (lo·lo dropped)
// ---------------------------------------------------------------------------
__device__ __forceinline__ uint2 splt2(float x0, float x1){
    unsigned hp;  // {x1_hi | x0_hi}
    asm("cvt.rn.bf16x2.f32 %0, %1, %2;" : "=r"(hp) : "f"(x1), "f"(x0));
    float h0 = __uint_as_float(hp << 16);
    float h1 = __uint_as_float(hp & 0xffff0000u);
    unsigned lp;
    asm("cvt.rn.bf16x2.f32 %0, %1, %2;" : "=r"(lp) : "f"(x1 - h1), "f"(x0 - h0));
    return make_uint2(hp, lp);
}
__device__ __forceinline__ void mma_bf16(float* d, const unsigned* a, const unsigned* b){
    asm volatile(
        "mma.sync.aligned.m16n8k16.row.col.f32.bf16.bf16.f32 "
        "{%0,%1,%2,%3}, {%4,%5,%6,%7}, {%8,%9}, {%0,%1,%2,%3};"
        : "+f"(d[0]), "+f"(d[1]), "+f"(d[2]), "+f"(d[3])
        : "r"(a[0]), "r"(a[1]), "r"(a[2]), "r"(a[3]),
          "r"(b[0]), "r"(b[1]));
}
__device__ __forceinline__ void cpa16(void* sdst, const void* gsrc){
    unsigned s = (unsigned)__cvta_generic_to_shared(sdst);
    asm volatile("cp.async.ca.shared.global [%0], [%1], 16;" :: "r"(s), "l"(gsrc));
}
#define CP_COMMIT()  asm volatile("cp.async.commit_group;")
#define CP_WAIT1()   asm volatile("cp.async.wait_group 1;" ::: "memory")

// ---------------------------------------------------------------------------
// K0: pre-split X, Wq, Wv into {hi,lo} bf16x2 pairs. 16 floats/thread.
// grid 544: blocks [0,512) -> X, [512,528) -> Wq, [528,544) -> Wv.
// ---------------------------------------------------------------------------
__global__ __launch_bounds__(256) void presplit_kernel(
    const float* __restrict__ X,
    const float* __restrict__ Wq,
    const float* __restrict__ Wv)
{
    int bid = blockIdx.x;
    const float* src; uint2* dst; int tl;
    if (bid < 512)      { src = X;  dst = g_xs;  tl = bid*256 + threadIdx.x; }
    else if (bid < 528) { src = Wq; dst = g_wqs; tl = (bid-512)*256 + threadIdx.x; }
    else                { src = Wv; dst = g_wvs; tl = (bid-528)*256 + threadIdx.x; }
    size_t f0 = (size_t)tl * 16;
    #pragma unroll
    for (int c = 0; c < 2; c++) {
        float4 a = *(const float4*)(src + f0 + c*8);
        float4 b = *(const float4*)(src + f0 + c*8 + 4);
        uint2 p0 = splt2(a.x, a.y), p1 = splt2(a.z, a.w);
        uint2 p2 = splt2(b.x, b.y), p3 = splt2(b.z, b.w);
        *(uint4*)(dst + f0/2 + c*4)     = make_uint4(p0.x, p0.y, p1.x, p1.y);
        *(uint4*)(dst + f0/2 + c*4 + 2) = make_uint4(p2.x, p2.y, p3.x, p3.y);
    }
}

// Tiles: uint2{hi,lo} per k-pair, pitch 12 (no swizzle needed: 12g mod 16
// tiles bank windows {0,12,8,4}); 3-stage cp.async pipeline, 1 sync/slab.

// ---------------------------------------------------------------------------
// K1: fused Q+V projection + bias + RoPE.
// BM=128 BN=64 BK=16; grid (64, 4); 8 warps (4m x 2n), warp tile 32x32.
// dyn smem: As[3][128][12] | Bq[3][64][12] | Bv[3][64][12] = 72 KB.
// ---------------------------------------------------------------------------
#define QV_SMEM (3*(128*12 + 64*12 + 64*12)*8)
__global__ __launch_bounds__(256, 2) void qv2_tc(
    const float* __restrict__ bq, const float* __restrict__ bv)
{
    extern __shared__ __align__(16) uint2 dyn[];
    uint2 (*As)[128][12] = (uint2(*)[128][12])(dyn);
    uint2 (*Bq)[64][12]  = (uint2(*)[64][12])(dyn + 3*128*12);
    uint2 (*Bv)[64][12]  = (uint2(*)[64][12])(dyn + 3*128*12 + 3*64*12);

    const int t = threadIdx.x;
    const int lane = t & 31, warp = t >> 5;
    const int g = lane >> 2, tg = lane & 3;
    const int wm = warp & 3, wn = warp >> 2;
    const int m0 = blockIdx.x * 128;
    const int nb = blockIdx.y * 64;

    const int crow = t >> 2;            // 0..63
    const int cjo  = (t & 3) * 2;       // pair offset 0,2,4,6

    float accQ[2][4][4] = {};
    float accV[2][4][4] = {};

    #define QV_ISSUE(s, kp)                                                      \
        cpa16(&As[s][crow][cjo],    g_xs  + (size_t)(m0+crow)*128 + (kp) + cjo); \
        cpa16(&As[s][crow+64][cjo], g_xs  + (size_t)(m0+crow+64)*128 + (kp) + cjo); \
        cpa16(&Bq[s][crow][cjo],    g_wqs + (size_t)(nb+crow)*128 + (kp) + cjo); \
        cpa16(&Bv[s][crow][cjo],    g_wvs + (size_t)(nb+crow)*128 + (kp) + cjo); \
        CP_COMMIT();

    QV_ISSUE(0, 0);
    QV_ISSUE(1, 8);

    #pragma unroll
    for (int it = 0; it < 16; it++) {
        const int cur = it % 3;
        CP_WAIT1();
        __syncthreads();
        if (it + 2 < 16) { QV_ISSUE((it+2)%3, (it+2)*8); }
        {
            const int ka = tg, kb2 = tg + 4;
            unsigned aH[2][4], aL[2][4], bH[4][2], bL[4][2];
            #pragma unroll
            for (int mi = 0; mi < 2; mi++) {
                int r = wm*32 + mi*16 + g;
                uint2 q;
                q = As[cur][r  ][ka];  aH[mi][0]=q.x; aL[mi][0]=q.y;
                q = As[cur][r+8][ka];  aH[mi][1]=q.x; aL[mi][1]=q.y;
                q = As[cur][r  ][kb2]; aH[mi][2]=q.x; aL[mi][2]=q.y;
                q = As[cur][r+8][kb2]; aH[mi][3]=q.x; aL[mi][3]=q.y;
            }
            #pragma unroll
            for (int ni = 0; ni < 4; ni++) {
                int nn = wn*32 + ni*8 + g;
                uint2 q;
                q = Bq[cur][nn][ka];  bH[ni][0]=q.x; bL[ni][0]=q.y;
                q = Bq[cur][nn][kb2]; bH[ni][1]=q.x; bL[ni][1]=q.y;
            }
            #pragma unroll
            for (int mi = 0; mi < 2; mi++)
                #pragma unroll
                for (int ni = 0; ni < 4; ni++) {
                    mma_bf16(accQ[mi][ni], aH[mi], bH[ni]);
                    mma_bf16(accQ[mi][ni], aH[mi], bL[ni]);
                    mma_bf16(accQ[mi][ni], aL[mi], bH[ni]);
                }
            #pragma unroll
            for (int ni = 0; ni < 4; ni++) {
                int nn = wn*32 + ni*8 + g;
                uint2 q;
                q = Bv[cur][nn][ka];  bH[ni][0]=q.x; bL[ni][0]=q.y;
                q = Bv[cur][nn][kb2]; bH[ni][1]=q.x; bL[ni][1]=q.y;
            }
            #pragma unroll
            for (int mi = 0; mi < 2; mi++)
                #pragma unroll
                for (int ni = 0; ni < 4; ni++) {
                    mma_bf16(accV[mi][ni], aH[mi], bH[ni]);
                    mma_bf16(accV[mi][ni], aH[mi], bL[ni]);
                    mma_bf16(accV[mi][ni], aL[mi], bH[ni]);
                }
        }
    }
    #undef QV_ISSUE

    // Epilogue: bias + RoPE; write f32 (for mw) and split form of xq (for out).
    const float th = (nb < 128) ? 1.0f : 1e-4f;
    #pragma unroll
    for (int mi = 0; mi < 2; mi++) {
        #pragma unroll
        for (int half = 0; half < 2; half++) {
            int r = m0 + wm*32 + mi*16 + g + half*8;
            float pos = (float)((r & (S_-1)) + 1);     // 1-indexed position
            float sv, cv; sincosf(pos * th, &sv, &cv);
            #pragma unroll
            for (int ni = 0; ni < 4; ni++) {
                int d = nb + wn*32 + ni*8 + 2*tg;
                float xe, xo;
                xe = accQ[mi][ni][half*2+0] + bq[d];
                xo = accQ[mi][ni][half*2+1] + bq[d+1];
                float2 oq = make_float2(xe*sv - xo*cv, xe*cv + xo*sv);
                *(float2*)(g_xq + (size_t)r*D_ + d) = oq;
                g_xqs[(size_t)r*128 + d/2] = splt2(oq.x, oq.y);
                xe = accV[mi][ni][half*2+0] + bv[d];
                xo = accV[mi][ni][half*2+1] + bv[d+1];
                *(float2*)(g_xv + (size_t)r*D_ + d) = make_float2(xe*sv - xo*cv, xe*cv + xo*sv);
            }
        }
    }
}

// ---------------------------------------------------------------------------
// K2 (fused): per (b,h): M[e][f] = (1/4) * sum_s xq[..e]*xv[..f]  (in smem),
// then W2T[b][n][16h+e] = sum_f M[e][f] * wo[n][16h+f], stored SPLIT.
// ---------------------------------------------------------------------------
__global__ __launch_bounds__(256) void mw_kernel(const float* __restrict__ Wo)
{
    __shared__ __align__(16) char smem_raw[38912];
    float (*qs)[20]       = (float(*)[20])(smem_raw);
    float (*vs)[20]       = (float(*)[20])(smem_raw + 10240);
    float (*part)[16][17] = (float(*)[16][17])(smem_raw + 20480);
    float (*wos)[20]      = (float(*)[20])(smem_raw);            // phase2 overlay
    __shared__ float Ms[16][16];

    const int bh = blockIdx.x, b = bh >> 4, h = bh & 15;
    const float* __restrict__ q = g_xq + (size_t)b*S_*D_ + h*16;
    const float* __restrict__ v = g_xv + (size_t)b*S_*D_ + h*16;
    const int t = threadIdx.x;
    const int grp = t >> 4, lt = t & 15;
    const int e4 = (lt >> 2) * 4, f4 = (lt & 3) * 4;
    float c[4][4] = {};

    for (int chunk = 0; chunk < 8; chunk++) {
        int sb = chunk * 128;
        #pragma unroll
        for (int i = 0; i < 2; i++) {
            int idx = t + i*256;
            int row = idx >> 2, c4 = (idx & 3) * 4;
            *(float4*)&qs[row][c4] = *(const float4*)(q + (size_t)(sb+row)*D_ + c4);
            *(float4*)&vs[row][c4] = *(const float4*)(v + (size_t)(sb+row)*D_ + c4);
        }
        __syncthreads();
        int r0 = grp * 8;
        #pragma unroll
        for (int ss = 0; ss < 8; ss++) {
            float4 q4 = *(const float4*)&qs[r0+ss][e4];
            float4 v4 = *(const float4*)&vs[r0+ss][f4];
            c[0][0] += q4.x*v4.x; c[0][1] += q4.x*v4.y; c[0][2] += q4.x*v4.z; c[0][3] += q4.x*v4.w;
            c[1][0] += q4.y*v4.x; c[1][1] += q4.y*v4.y; c[1][2] += q4.y*v4.z; c[1][3] += q4.y*v4.w;
            c[2][0] += q4.z*v4.x; c[2][1] += q4.z*v4.y; c[2][2] += q4.z*v4.z; c[2][3] += q4.z*v4.w;
            c[3][0] += q4.w*v4.x; c[3][1] += q4.w*v4.y; c[3][2] += q4.w*v4.z; c[3][3] += q4.w*v4.w;
        }
        __syncthreads();
    }
    #pragma unroll
    for (int i = 0; i < 4; i++)
        #pragma unroll
        for (int j = 0; j < 4; j++)
            part[grp][e4+i][f4+j] = c[i][j];
    __syncthreads();
    {
        int e = t >> 4, f = t & 15;
        float s = 0.f;
        #pragma unroll
        for (int gg = 0; gg < 16; gg++) s += part[gg][e][f];
        __syncthreads();                 // all part reads done before wos overwrite
        Ms[e][f] = s * 0.25f;            // 1/sqrt(HD=16)
    }
    #pragma unroll
    for (int i = 0; i < 4; i++) {
        int idx = t + i*256;
        int row = idx >> 2, c4 = (idx & 3) * 4;
        *(float4*)&wos[row][c4] = *(const float4*)(Wo + (size_t)row*D_ + h*16 + c4);
    }
    __syncthreads();
    const int n = t;
    float vals[16];
    #pragma unroll
    for (int e = 0; e < 16; e++) {
        float a = 0.f;
        #pragma unroll
        for (int f = 0; f < 16; f++) a += Ms[e][f] * wos[n][f];
        vals[e] = a;
    }
    uint2* outp = g_w2s + (size_t)b*D_*128 + (size_t)n*128 + h*8;  // [n][kpair]
    #pragma unroll
    for (int e = 0; e < 16; e += 2)
        outp[e/2] = splt2(vals[e], vals[e+1]);
}

// ---------------------------------------------------------------------------
// K3: out_b = xq_b @ W2T_b^T + bo. BM=128 BN=128 BK=16; grid (2, 8, 8).
// dyn smem: As[3][128][12] | Bs[3][128][12] = 72 KB.
// ---------------------------------------------------------------------------
#define OUT_SMEM (3*(128*12 + 128*12)*8)
__global__ __launch_bounds__(256, 2) void out_tc(
    const float* __restrict__ bo, float* __restrict__ out)
{
    extern __shared__ __align__(16) uint2 dyn2[];
    uint2 (*As)[128][12] = (uint2(*)[128][12])(dyn2);
    uint2 (*Bs)[128][12] = (uint2(*)[128][12])(dyn2 + 3*128*12);

    const int t = threadIdx.x;
    const int lane = t & 31, warp = t >> 5;
    const int g = lane >> 2, tg = lane & 3;
    const int wm = warp & 3, wn = warp >> 2;
    const int bz = blockIdx.z;
    const int m0 = blockIdx.y * 128, n0 = blockIdx.x * 128;
    const uint2* __restrict__ Axs = g_xqs + (size_t)bz*S_*128;
    const uint2* __restrict__ Bws = g_w2s + (size_t)bz*D_*128;

    const int crow = t >> 2;
    const int cjo  = (t & 3) * 2;

    float acc[2][8][4] = {};

    #define OUT_ISSUE(s, kp)                                                         \
        cpa16(&As[s][crow][cjo],    Axs + (size_t)(m0+crow)*128 + (kp) + cjo);       \
        cpa16(&As[s][crow+64][cjo], Axs + (size_t)(m0+crow+64)*128 + (kp) + cjo);    \
        cpa16(&Bs[s][crow][cjo],    Bws + (size_t)(n0+crow)*128 + (kp) + cjo);       \
        cpa16(&Bs[s][crow+64][cjo], Bws + (size_t)(n0+crow+64)*128 + (kp) + cjo);    \
        CP_COMMIT();

    OUT_ISSUE(0, 0);
    OUT_ISSUE(1, 8);

    #pragma unroll
    for (int it = 0; it < 16; it++) {
        const int cur = it % 3;
        CP_WAIT1();
        __syncthreads();
        if (it + 2 < 16) { OUT_ISSUE((it+2)%3, (it+2)*8); }
        {
            const int ka = tg, kb2 = tg + 4;
            unsigned aH[2][4], aL[2][4], bH[4][2], bL[4][2];
            #pragma unroll
            for (int mi = 0; mi < 2; mi++) {
                int r = wm*32 + mi*16 + g;
                uint2 q;
                q = As[cur][r  ][ka];  aH[mi][0]=q.x; aL[mi][0]=q.y;
                q = As[cur][r+8][ka];  aH[mi][1]=q.x; aL[mi][1]=q.y;
                q = As[cur][r  ][kb2]; aH[mi][2]=q.x; aL[mi][2]=q.y;
                q = As[cur][r+8][kb2]; aH[mi][3]=q.x; aL[mi][3]=q.y;
            }
            #pragma unroll
            for (int nh = 0; nh < 2; nh++) {
                #pragma unroll
                for (int ni = 0; ni < 4; ni++) {
                    int nn = wn*64 + (nh*4+ni)*8 + g;
                    uint2 q;
                    q = Bs[cur][nn][ka];  bH[ni][0]=q.x; bL[ni][0]=q.y;
                    q = Bs[cur][nn][kb2]; bH[ni][1]=q.x; bL[ni][1]=q.y;
                }
                #pragma unroll
                for (int mi = 0; mi < 2; mi++)
                    #pragma unroll
                    for (int ni = 0; ni < 4; ni++) {
                        mma_bf16(acc[mi][nh*4+ni], aH[mi], bH[ni]);
                        mma_bf16(acc[mi][nh*4+ni], aH[mi], bL[ni]);
                        mma_bf16(acc[mi][nh*4+ni], aL[mi], bH[ni]);
                    }
            }
        }
    }
    #undef OUT_ISSUE

    #pragma unroll
    for (int mi = 0; mi < 2; mi++) {
        #pragma unroll
        for (int half = 0; half < 2; half++) {
            int r = bz*S_ + m0 + wm*32 + mi*16 + g + half*8;
            #pragma unroll
            for (int ni = 0; ni < 8; ni++) {
                int d = n0 + wn*64 + ni*8 + 2*tg;
                float2 o = make_float2(acc[mi][ni][half*2+0] + bo[d],
                                       acc[mi][ni][half*2+1] + bo[d+1]);
                *(float2*)(out + (size_t)r*D_ + d) = o;
            }
        }
    }
}

// ---------------------------------------------------------------------------
extern "C" void kernel_launch(void* const* d_in, const int* in_sizes, int n_in,
                              void* d_out, int out_size)
{
    (void)in_sizes; (void)n_in; (void)out_size;
    const float* x   = (const float*)d_in[0];
    const float* wqw = (const float*)d_in[1];
    const float* wqb = (const float*)d_in[2];
    // d_in[3], d_in[4] = wk_w, wk_b : dead in reference
    const float* wvw = (const float*)d_in[5];
    const float* wvb = (const float*)d_in[6];
    const float* wow = (const float*)d_in[7];
    const float* wob = (const float*)d_in[8];
    float* out = (float*)d_out;

    cudaFuncSetAttribute(qv2_tc, cudaFuncAttributeMaxDynamicSharedMemorySize, QV_SMEM);
    cudaFuncSetAttribute(out_tc, cudaFuncAttributeMaxDynamicSharedMemorySize, OUT_SMEM);

    presplit_kernel<<<544, 256>>>(x, wqw, wvw);
    qv2_tc<<<dim3(64, 4), 256, QV_SMEM>>>(wqb, wvb);
    mw_kernel<<<128, 256>>>(wow);
    out_tc<<<dim3(2, 8, 8), 256, OUT_SMEM>>>(wob, out);
}